// round 6
// baseline (speedup 1.0000x reference)
#include <cuda_runtime.h>
#include <math.h>
#include <stdint.h>

#define NN 50000
#define FF 128
#define CC 512
#define EE 800000
#define HH 256

#define OFF_ADJ   (CC*FF)
#define OFF_BATCH (OFF_ADJ + CC*CC)
#define OFF_S     (OFF_BATCH + CC)

// ---------------- scratch ----------------------------------------------------
__device__ __align__(16) float g_l[(size_t)NN * CC];
__device__ __align__(16) float g_z[(size_t)NN * HH];
__device__ __align__(16) float g_t[(size_t)NN * HH];
__device__ float g_inv[NN];
__device__ int   g_deg[NN];
__device__ int   g_off[NN + 1];
__device__ int   g_cur[NN];
__device__ int   g_csr_src[EE];
__device__ float g_csr_cf[EE];
__device__ int   g_cluster[NN];
__device__ float g_hs[NN];
__device__ int   g_sdeg[NN];
__device__ float g_invs[NN];
__device__ float g_sagg[NN];
__device__ float g_score[NN];
__device__ int   g_icnt[CC];
__device__ int   g_segkey[CC];
__device__ int   g_segidx[CC];

__device__ __forceinline__ int fkey(float f) {
    int b = __float_as_int(f);
    return b < 0 ? (b ^ 0x7FFFFFFF) : b;
}
__device__ __forceinline__ float fdec(int k) {
    return __int_as_float(k < 0 ? (k ^ 0x7FFFFFFF) : k);
}

// ---------------- init / degree / scan / fill --------------------------------
__global__ void k_init(float* out) {
    int i = blockIdx.x * blockDim.x + threadIdx.x;
    int stride = gridDim.x * blockDim.x;
    for (int j = i; j < NN; j += stride) { g_deg[j] = 0; g_sdeg[j] = 0; g_sagg[j] = 0.f; }
    for (int j = i; j < CC; j += stride) {
        g_icnt[j] = 0; g_segkey[j] = (int)0x80000000; g_segidx[j] = NN;
        out[OFF_BATCH + j] = 0.f;
    }
    for (int j = i; j < CC * CC; j += stride) out[OFF_ADJ + j] = 0.f;
}

__global__ void k_deg(const int* __restrict__ ei) {
    int e = blockIdx.x * blockDim.x + threadIdx.x;
    if (e < EE) atomicAdd(&g_deg[ei[EE + e]], 1);
}

// single-block scan + inv + cur (so k_fill lands at profiled launch idx 3)
__global__ void __launch_bounds__(1024) k_scanall() {
    __shared__ int ssum[1024];
    int t = threadIdx.x;
    const int chunk = (NN + 1023) / 1024;
    int b = t * chunk, e = min(b + chunk, NN);
    int s = 0;
    for (int i = b; i < e; i++) s += g_deg[i];
    ssum[t] = s;
    __syncthreads();
    for (int off = 1; off < 1024; off <<= 1) {
        int v = (t >= off) ? ssum[t - off] : 0;
        __syncthreads();
        ssum[t] += v;
        __syncthreads();
    }
    int run = (t > 0) ? ssum[t - 1] : 0;
    for (int i = b; i < e; i++) {
        int d = g_deg[i];
        g_off[i] = run;
        g_cur[i] = run;
        g_inv[i] = rsqrtf((float)d + 1.0f);
        run += d;
    }
    if (t == 1023) g_off[NN] = ssum[1023];
}

__global__ void k_fill(const int* __restrict__ ei) {   // PROFILED (launch idx 3)
    int e = blockIdx.x * blockDim.x + threadIdx.x;
    if (e >= EE) return;
    int s = ei[e], d = ei[EE + e];
    int p = atomicAdd(&g_cur[d], 1);
    g_csr_src[p] = s;
    g_csr_cf[p] = g_inv[s] * g_inv[d];
}

// ---------------- aggregation: R2's exact block-per-node variant -------------
template <int D, bool EPI>
__global__ void __launch_bounds__(D) k_agg(const float* __restrict__ h,
                                           float* __restrict__ z,
                                           const float* __restrict__ bias) {
    int i = blockIdx.x;
    int t = threadIdx.x;
    int beg = g_off[i], end = g_off[i + 1];
    float inv = g_inv[i];
    float acc = inv * inv * __ldg(h + (size_t)i * D + t);

    __shared__ int   s_src[128];
    __shared__ float s_cf[128];
    for (int e0 = beg; e0 < end; e0 += 128) {
        int m = min(128, end - e0);
        __syncthreads();
        if (t < m) {
            s_src[t] = g_csr_src[e0 + t];
            s_cf[t]  = g_csr_cf[e0 + t];
        }
        __syncthreads();
        for (int j = 0; j < m; j++) {
            const float* hr = h + (size_t)s_src[j] * D + t;
            acc = fmaf(s_cf[j], __ldg(hr), acc);
        }
    }
    if (EPI) acc = fmaxf(acc + bias[t], 0.f);
    z[(size_t)i * D + t] = acc;
}

// ---------------- split-tf32 TC GEMM, 128x64 tile, 3 CTA/SM target -----------
__device__ __forceinline__ uint32_t f2tf(float f) {
    uint32_t r;
    asm("cvt.rna.tf32.f32 %0, %1;" : "=r"(r) : "f"(f));
    return r;
}
__device__ __forceinline__ void mma_tf32(float4& d,
                                         uint32_t a0, uint32_t a1, uint32_t a2, uint32_t a3,
                                         uint32_t b0, uint32_t b1) {
    asm volatile("mma.sync.aligned.m16n8k8.row.col.f32.tf32.tf32.f32 "
                 "{%0,%1,%2,%3}, {%4,%5,%6,%7}, {%8,%9}, {%0,%1,%2,%3};"
                 : "+f"(d.x), "+f"(d.y), "+f"(d.z), "+f"(d.w)
                 : "r"(a0), "r"(a1), "r"(a2), "r"(a3), "r"(b0), "r"(b1));
}

__global__ void __launch_bounds__(256, 3) k_tcgemm(const float* __restrict__ A,
                                                   const float* __restrict__ B,
                                                   const float* __restrict__ bias,
                                                   float* __restrict__ Cm,
                                                   int M, int K, int Nc, int epi) {
    __shared__ uint32_t Ah[2][8][132];
    __shared__ uint32_t Al[2][8][132];
    __shared__ uint32_t Bh[2][8][68];
    __shared__ uint32_t Bl[2][8][68];

    const int tid = threadIdx.x;
    const int wid = tid >> 5;
    const int lane = tid & 31;
    const int q = lane >> 2;
    const int t4 = lane & 3;
    const int m0 = (wid & 3) * 32;
    const int n0 = (wid >> 2) * 32;

    const int rowBase = blockIdx.y * 128;
    const int colBase = blockIdx.x * 64;

    const int ar = tid >> 1;
    const int ac4 = (tid & 1) * 4;
    const int br = tid >> 4;              // 0..15 (only tid<128 valid: 0..7)
    const int bc4 = (tid & 15) * 4;       // 0..60
    const bool aok = (rowBase + ar) < M;
    const bool bldr = tid < 128;
    const float* Aptr = A + (size_t)(rowBase + ar) * K + ac4;
    const float* Bptr = B + (size_t)br * Nc + colBase + bc4;

    float4 acc[2][4];
#pragma unroll
    for (int mi = 0; mi < 2; mi++)
#pragma unroll
        for (int ni = 0; ni < 4; ni++) acc[mi][ni] = make_float4(0.f, 0.f, 0.f, 0.f);

#define SPLIT_STORE(arrH, arrL, BUF, D0, D1, V)                      \
    {                                                                \
        uint32_t h_ = f2tf(V);                                       \
        float lo_ = (V) - __uint_as_float(h_);                       \
        arrH[BUF][D0][D1] = h_;                                      \
        arrL[BUF][D0][D1] = f2tf(lo_);                               \
    }
#define LOAD_TILE(BUF, K0)                                                        \
    {                                                                             \
        float4 va = aok ? *(const float4*)(Aptr + (K0))                           \
                        : make_float4(0.f, 0.f, 0.f, 0.f);                        \
        SPLIT_STORE(Ah, Al, BUF, ac4 + 0, ar, va.x)                               \
        SPLIT_STORE(Ah, Al, BUF, ac4 + 1, ar, va.y)                               \
        SPLIT_STORE(Ah, Al, BUF, ac4 + 2, ar, va.z)                               \
        SPLIT_STORE(Ah, Al, BUF, ac4 + 3, ar, va.w)                               \
        if (bldr) {                                                               \
            float4 vb = *(const float4*)(Bptr + (size_t)(K0) * Nc);               \
            SPLIT_STORE(Bh, Bl, BUF, br, bc4 + 0, vb.x)                           \
            SPLIT_STORE(Bh, Bl, BUF, br, bc4 + 1, vb.y)                           \
            SPLIT_STORE(Bh, Bl, BUF, br, bc4 + 2, vb.z)                           \
            SPLIT_STORE(Bh, Bl, BUF, br, bc4 + 3, vb.w)                           \
        }                                                                         \
    }

#define COMPUTE_TILE(BUF)                                                          \
    {                                                                              \
        uint32_t ah[2][4], al[2][4];                                               \
        _Pragma("unroll")                                                          \
        for (int mi = 0; mi < 2; mi++) {                                           \
            int mrow = m0 + mi * 16;                                               \
            ah[mi][0] = Ah[BUF][t4][mrow + q];                                     \
            ah[mi][1] = Ah[BUF][t4][mrow + q + 8];                                 \
            ah[mi][2] = Ah[BUF][t4 + 4][mrow + q];                                 \
            ah[mi][3] = Ah[BUF][t4 + 4][mrow + q + 8];                             \
            al[mi][0] = Al[BUF][t4][mrow + q];                                     \
            al[mi][1] = Al[BUF][t4][mrow + q + 8];                                 \
            al[mi][2] = Al[BUF][t4 + 4][mrow + q];                                 \
            al[mi][3] = Al[BUF][t4 + 4][mrow + q + 8];                             \
        }                                                                          \
        _Pragma("unroll")                                                          \
        for (int ni = 0; ni < 4; ni++) {                                           \
            int ncol = n0 + ni * 8 + q;                                            \
            uint32_t bh0 = Bh[BUF][t4][ncol];                                      \
            uint32_t bh1 = Bh[BUF][t4 + 4][ncol];                                  \
            uint32_t bl0 = Bl[BUF][t4][ncol];                                      \
            uint32_t bl1 = Bl[BUF][t4 + 4][ncol];                                  \
            _Pragma("unroll")                                                      \
            for (int mi = 0; mi < 2; mi++) {                                       \
                mma_tf32(acc[mi][ni], ah[mi][0], ah[mi][1], ah[mi][2], ah[mi][3],  \
                         bh0, bh1);                                                \
                mma_tf32(acc[mi][ni], ah[mi][0], ah[mi][1], ah[mi][2], ah[mi][3],  \
                         bl0, bl1);                                                \
                mma_tf32(acc[mi][ni], al[mi][0], al[mi][1], al[mi][2], al[mi][3],  \
                         bh0, bh1);                                                \
            }                                                                      \
        }                                                                          \
    }

    LOAD_TILE(0, 0)
    __syncthreads();

    int buf = 0;
    for (int k0 = 8; k0 < K; k0 += 8) {
        COMPUTE_TILE(buf)
        LOAD_TILE(buf ^ 1, k0)
        __syncthreads();
        buf ^= 1;
    }
    COMPUTE_TILE(buf)

#pragma unroll
    for (int mi = 0; mi < 2; mi++) {
#pragma unroll
        for (int ni = 0; ni < 4; ni++) {
            int col = colBase + n0 + ni * 8 + 2 * t4;
            float bb0 = 0.f, bb1 = 0.f;
            if (epi) { bb0 = bias[col]; bb1 = bias[col + 1]; }
            int r0 = rowBase + m0 + mi * 16 + q;
            int r1 = r0 + 8;
            float4 v = acc[mi][ni];
            float o0 = v.x + bb0, o1 = v.y + bb1, o2 = v.z + bb0, o3 = v.w + bb1;
            if (epi) {
                o0 = fmaxf(o0, 0.f); o1 = fmaxf(o1, 0.f);
                o2 = fmaxf(o2, 0.f); o3 = fmaxf(o3, 0.f);
            }
            if (r0 < M) *(float2*)(Cm + (size_t)r0 * Nc + col) = make_float2(o0, o1);
            if (r1 < M) *(float2*)(Cm + (size_t)r1 * Nc + col) = make_float2(o2, o3);
        }
    }
}

// ---------------- softmax + argmax (first-max tie rule) ----------------------
__global__ void __launch_bounds__(256) k_softmax(const float* __restrict__ logits,
                                                 float* __restrict__ S) {
    int i = blockIdx.x;
    int t = threadIdx.x;
    int w = t >> 5, lane = t & 31;
    const float* row = logits + (size_t)i * CC;
    float v0 = row[t], v1 = row[t + 256];
    float bv = v0; int bi = t;
    if (v1 > bv) { bv = v1; bi = t + 256; }

#pragma unroll
    for (int off = 16; off > 0; off >>= 1) {
        float ov = __shfl_xor_sync(0xFFFFFFFF, bv, off);
        int   oi = __shfl_xor_sync(0xFFFFFFFF, bi, off);
        if (ov > bv || (ov == bv && oi < bi)) { bv = ov; bi = oi; }
    }
    __shared__ float swv[8];
    __shared__ int   swi[8];
    if (lane == 0) { swv[w] = bv; swi[w] = bi; }
    __syncthreads();
    float m = swv[0]; int am = swi[0];
#pragma unroll
    for (int k = 1; k < 8; k++) {
        float ov = swv[k]; int oi = swi[k];
        if (ov > m || (ov == m && oi < am)) { m = ov; am = oi; }
    }
    if (t == 0) g_cluster[i] = am;

    float e0 = expf(v0 - m), e1 = expf(v1 - m);
    float s = e0 + e1;
#pragma unroll
    for (int off = 16; off > 0; off >>= 1)
        s += __shfl_xor_sync(0xFFFFFFFF, s, off);
    __shared__ float sws[8];
    if (lane == 0) sws[w] = s;
    __syncthreads();
    float tot = sws[0] + sws[1] + sws[2] + sws[3] + sws[4] + sws[5] + sws[6] + sws[7];
    float invsum = 1.0f / tot;
    S[(size_t)i * CC + t]       = e0 * invsum;
    S[(size_t)i * CC + t + 256] = e1 * invsum;
}

// ---------------- score layer -------------------------------------------------
__global__ void k_hs(const float* __restrict__ x, const float* __restrict__ Ws) {
    int g = blockIdx.x * blockDim.x + threadIdx.x;
    int w = g >> 5, lane = g & 31;
    if (w >= NN) return;
    float4 xv = __ldg((const float4*)x + (size_t)w * 32 + lane);
    float4 wv = __ldg((const float4*)Ws + lane);
    float s = xv.x * wv.x + xv.y * wv.y + xv.z * wv.z + xv.w * wv.w;
#pragma unroll
    for (int off = 16; off > 0; off >>= 1) s += __shfl_down_sync(0xFFFFFFFF, s, off);
    if (lane == 0) g_hs[w] = s;
}

__global__ void k_intradeg(const int* __restrict__ ei) {
    int e = blockIdx.x * blockDim.x + threadIdx.x;
    if (e >= EE) return;
    int s = ei[e], d = ei[EE + e];
    int cs = g_cluster[s], cd = g_cluster[d];
    if (cs == cd) {
        atomicAdd(&g_sdeg[d], 1);
        atomicAdd(&g_icnt[cs], 1);
    }
}

__global__ void k_invs() {
    int i = blockIdx.x * blockDim.x + threadIdx.x;
    if (i < NN) g_invs[i] = rsqrtf((float)g_sdeg[i] + 1.0f);
}

__global__ void k_sagg(const int* __restrict__ ei) {
    int e = blockIdx.x * blockDim.x + threadIdx.x;
    if (e >= EE) return;
    int s = ei[e], d = ei[EE + e];
    if (g_cluster[s] == g_cluster[d])
        atomicAdd(&g_sagg[d], g_invs[s] * g_invs[d] * g_hs[s]);
}

__global__ void k_score(const float* __restrict__ bs) {
    int i = blockIdx.x * blockDim.x + threadIdx.x;
    if (i >= NN) return;
    float inv = g_invs[i];
    float v = g_sagg[i] + inv * inv * g_hs[i] + bs[0];
    float sc = tanhf(v);
    g_score[i] = sc;
    atomicMax(&g_segkey[g_cluster[i]], fkey(sc));
}

__global__ void k_segidx() {
    int i = blockIdx.x * blockDim.x + threadIdx.x;
    if (i >= NN) return;
    int c = g_cluster[i];
    float mx = fdec(g_segkey[c]);
    if (g_score[i] >= mx) atomicMin(&g_segidx[c], i);
}

// ---------------- pooling + adjacency ----------------------------------------
__global__ void __launch_bounds__(128) k_pool(const float* __restrict__ x,
                                              float* __restrict__ out) {
    int c = blockIdx.x;
    bool ne = g_icnt[c] > 0;
    float alpha = ne ? fdec(g_segkey[c]) : 0.f;
    int idx = min(g_segidx[c], NN - 1);
    out[(size_t)c * FF + threadIdx.x] = x[(size_t)idx * FF + threadIdx.x] * alpha;
}

__global__ void k_adj(const int* __restrict__ ei, float* __restrict__ out) {
    int e = blockIdx.x * blockDim.x + threadIdx.x;
    if (e >= EE) return;
    int cs = g_cluster[ei[e]], cd = g_cluster[ei[EE + e]];
    if (cs != cd && g_icnt[cs] > 0 && g_icnt[cd] > 0)
        out[OFF_ADJ + (size_t)cs * CC + cd] = 1.0f;
}

// ---------------- launch ------------------------------------------------------
extern "C" void kernel_launch(void* const* d_in, const int* in_sizes, int n_in,
                              void* d_out, int out_size) {
    const float* x   = (const float*)d_in[0];
    const int*   ei  = (const int*)d_in[1];
    const float* W1  = (const float*)d_in[3];
    const float* b1  = (const float*)d_in[4];
    const float* W2  = (const float*)d_in[5];
    const float* b2  = (const float*)d_in[6];
    const float* W3  = (const float*)d_in[7];
    const float* b3  = (const float*)d_in[8];
    const float* Ws  = (const float*)d_in[9];
    const float* bs  = (const float*)d_in[10];
    float* out = (float*)d_out;

    const int EB = (EE + 255) / 256;
    const int NB = (NN + 255) / 256;

    k_init<<<512, 256>>>(out);          // 0
    k_deg<<<EB, 256>>>(ei);             // 1
    k_scanall<<<1, 1024>>>();           // 2 (scan + inv + cur)
    k_fill<<<EB, 256>>>(ei);            // 3  [PROFILED]

    // layer 1: z = agg(x) (128-wide); h1 = relu(z @ W1 + b1)
    k_agg<128, false><<<NN, 128>>>(x, g_z, (const float*)0);
    {
        dim3 g(HH / 64, (NN + 127) / 128);
        k_tcgemm<<<g, 256>>>(g_z, W1, b1, g_t, NN, FF, HH, 1);
    }
    // layer 2
    k_agg<256, false><<<NN, 256>>>(g_t, g_z, (const float*)0);
    {
        dim3 g(HH / 64, (NN + 127) / 128);
        k_tcgemm<<<g, 256>>>(g_z, W2, b2, g_t, NN, HH, HH, 1);
    }
    // layer 3
    k_agg<256, false><<<NN, 256>>>(g_t, g_z, (const float*)0);
    {
        dim3 g(CC / 64, (NN + 127) / 128);
        k_tcgemm<<<g, 256>>>(g_z, W3, b3, g_l, NN, HH, CC, 1);
    }

    k_softmax<<<NN, 256>>>(g_l, out + OFF_S);

    k_hs<<<(NN * 32 + 255) / 256, 256>>>(x, Ws);
    k_intradeg<<<EB, 256>>>(ei);
    k_invs<<<NB, 256>>>();
    k_sagg<<<EB, 256>>>(ei);
    k_score<<<NB, 256>>>(bs);
    k_segidx<<<NB, 256>>>();
    k_pool<<<CC, 128>>>(x, out);
    k_adj<<<EB, 256>>>(ei, out);

    (void)in_sizes; (void)n_in; (void)out_size;
}

// round 7
// speedup vs baseline: 1.0631x; 1.0631x over previous
#include <cuda_runtime.h>
#include <math.h>
#include <stdint.h>

#define NN 50000
#define FF 128
#define CC 512
#define EE 800000
#define HH 256

#define OFF_ADJ   (CC*FF)
#define OFF_BATCH (OFF_ADJ + CC*CC)
#define OFF_S     (OFF_BATCH + CC)

// ---------------- scratch ----------------------------------------------------
__device__ __align__(16) float g_l[(size_t)NN * CC];
__device__ __align__(16) float g_z[(size_t)NN * HH];
__device__ __align__(16) float g_t[(size_t)NN * HH];
__device__ float g_inv[NN];
__device__ int   g_deg[NN];
__device__ int   g_off[NN + 1];
__device__ int   g_cur[NN];
__device__ int   g_csr_src[EE];
__device__ float g_csr_cf[EE];
__device__ int   g_cluster[NN];
__device__ float g_hs[NN];
__device__ int   g_sdeg[NN];
__device__ float g_invs[NN];
__device__ float g_sagg[NN];
__device__ float g_score[NN];
__device__ int   g_icnt[CC];
__device__ int   g_segkey[CC];
__device__ int   g_segidx[CC];

__device__ __forceinline__ int fkey(float f) {
    int b = __float_as_int(f);
    return b < 0 ? (b ^ 0x7FFFFFFF) : b;
}
__device__ __forceinline__ float fdec(int k) {
    return __int_as_float(k < 0 ? (k ^ 0x7FFFFFFF) : k);
}

// ---------------- init / degree / scan / fill --------------------------------
__global__ void k_init(float* out) {
    int i = blockIdx.x * blockDim.x + threadIdx.x;
    int stride = gridDim.x * blockDim.x;
    for (int j = i; j < NN; j += stride) { g_deg[j] = 0; g_sdeg[j] = 0; g_sagg[j] = 0.f; }
    for (int j = i; j < CC; j += stride) {
        g_icnt[j] = 0; g_segkey[j] = (int)0x80000000; g_segidx[j] = NN;
        out[OFF_BATCH + j] = 0.f;
    }
    for (int j = i; j < CC * CC; j += stride) out[OFF_ADJ + j] = 0.f;
}

__global__ void k_deg(const int* __restrict__ ei) {
    int e = blockIdx.x * blockDim.x + threadIdx.x;
    if (e < EE) atomicAdd(&g_deg[ei[EE + e]], 1);
}

__global__ void __launch_bounds__(1024) k_scanall() {
    __shared__ int ssum[1024];
    int t = threadIdx.x;
    const int chunk = (NN + 1023) / 1024;
    int b = t * chunk, e = min(b + chunk, NN);
    int s = 0;
    for (int i = b; i < e; i++) s += g_deg[i];
    ssum[t] = s;
    __syncthreads();
    for (int off = 1; off < 1024; off <<= 1) {
        int v = (t >= off) ? ssum[t - off] : 0;
        __syncthreads();
        ssum[t] += v;
        __syncthreads();
    }
    int run = (t > 0) ? ssum[t - 1] : 0;
    for (int i = b; i < e; i++) {
        int d = g_deg[i];
        g_off[i] = run;
        g_cur[i] = run;
        g_inv[i] = rsqrtf((float)d + 1.0f);
        run += d;
    }
    if (t == 1023) g_off[NN] = ssum[1023];
}

__global__ void k_fill(const int* __restrict__ ei) {
    int e = blockIdx.x * blockDim.x + threadIdx.x;
    if (e >= EE) return;
    int s = ei[e], d = ei[EE + e];
    int p = atomicAdd(&g_cur[d], 1);
    g_csr_src[p] = s;
    g_csr_cf[p] = g_inv[s] * g_inv[d];
}

// ---------------- aggregation: FEATURE-TILED (64-wide slices, L2-resident) ---
// grid: ((NN+3)/4, D/64), block 256. Each 64-lane group handles one node's
// 64-feature slice. All slice-0 blocks run before slice-1 => the 12.8MB h-slice
// stays L2-resident while the 800k random row-gathers hit it.
template <int D>
__global__ void __launch_bounds__(256) k_aggt(const float* __restrict__ h,
                                              float* __restrict__ z) {
    int sub = threadIdx.x >> 6;
    int lane = threadIdx.x & 63;
    int i = blockIdx.x * 4 + sub;
    if (i >= NN) return;
    int f = blockIdx.y * 64 + lane;
    const float* hf = h + f;

    int beg = g_off[i], end = g_off[i + 1];
    float inv = g_inv[i];
    float acc0 = inv * inv * __ldg(hf + (size_t)i * D);
    float acc1 = 0.f;

    int j = beg;
    for (; j + 8 <= end; j += 8) {
        int s0 = __ldg(g_csr_src + j + 0);
        int s1 = __ldg(g_csr_src + j + 1);
        int s2 = __ldg(g_csr_src + j + 2);
        int s3 = __ldg(g_csr_src + j + 3);
        int s4 = __ldg(g_csr_src + j + 4);
        int s5 = __ldg(g_csr_src + j + 5);
        int s6 = __ldg(g_csr_src + j + 6);
        int s7 = __ldg(g_csr_src + j + 7);
        float c0 = __ldg(g_csr_cf + j + 0);
        float c1 = __ldg(g_csr_cf + j + 1);
        float c2 = __ldg(g_csr_cf + j + 2);
        float c3 = __ldg(g_csr_cf + j + 3);
        float c4 = __ldg(g_csr_cf + j + 4);
        float c5 = __ldg(g_csr_cf + j + 5);
        float c6 = __ldg(g_csr_cf + j + 6);
        float c7 = __ldg(g_csr_cf + j + 7);
        float v0 = __ldg(hf + (size_t)s0 * D);
        float v1 = __ldg(hf + (size_t)s1 * D);
        float v2 = __ldg(hf + (size_t)s2 * D);
        float v3 = __ldg(hf + (size_t)s3 * D);
        float v4 = __ldg(hf + (size_t)s4 * D);
        float v5 = __ldg(hf + (size_t)s5 * D);
        float v6 = __ldg(hf + (size_t)s6 * D);
        float v7 = __ldg(hf + (size_t)s7 * D);
        acc0 = fmaf(c0, v0, acc0); acc1 = fmaf(c1, v1, acc1);
        acc0 = fmaf(c2, v2, acc0); acc1 = fmaf(c3, v3, acc1);
        acc0 = fmaf(c4, v4, acc0); acc1 = fmaf(c5, v5, acc1);
        acc0 = fmaf(c6, v6, acc0); acc1 = fmaf(c7, v7, acc1);
    }
    for (; j < end; j++) {
        int s0 = __ldg(g_csr_src + j);
        float c0 = __ldg(g_csr_cf + j);
        acc0 = fmaf(c0, __ldg(hf + (size_t)s0 * D), acc0);
    }
    z[(size_t)i * D + f] = acc0 + acc1;
}

// ---------------- split-tf32 TC GEMM (R5's measured 128x128 variant) ---------
__device__ __forceinline__ uint32_t f2tf(float f) {
    uint32_t r;
    asm("cvt.rna.tf32.f32 %0, %1;" : "=r"(r) : "f"(f));
    return r;
}
__device__ __forceinline__ void mma_tf32(float4& d,
                                         uint32_t a0, uint32_t a1, uint32_t a2, uint32_t a3,
                                         uint32_t b0, uint32_t b1) {
    asm volatile("mma.sync.aligned.m16n8k8.row.col.f32.tf32.tf32.f32 "
                 "{%0,%1,%2,%3}, {%4,%5,%6,%7}, {%8,%9}, {%0,%1,%2,%3};"
                 : "+f"(d.x), "+f"(d.y), "+f"(d.z), "+f"(d.w)
                 : "r"(a0), "r"(a1), "r"(a2), "r"(a3), "r"(b0), "r"(b1));
}

#define TCSTRIDE 136

__global__ void __launch_bounds__(256) k_tcgemm(const float* __restrict__ A,
                                                const float* __restrict__ B,
                                                const float* __restrict__ bias,
                                                float* __restrict__ Cm,
                                                int M, int K, int Nc, int epi) {
    __shared__ uint32_t Ah[2][8][TCSTRIDE];
    __shared__ uint32_t Al[2][8][TCSTRIDE];
    __shared__ uint32_t Bh[2][8][TCSTRIDE];
    __shared__ uint32_t Bl[2][8][TCSTRIDE];

    const int tid = threadIdx.x;
    const int wid = tid >> 5;
    const int lane = tid & 31;
    const int q = lane >> 2;
    const int t4 = lane & 3;
    const int m0 = (wid & 3) * 32;
    const int n0 = (wid >> 2) * 64;

    const int rowBase = blockIdx.y * 128;
    const int colBase = blockIdx.x * 128;

    const int ar = tid >> 1;
    const int ac4 = (tid & 1) * 4;
    const int br = tid >> 5;
    const int bc4 = (tid & 31) * 4;
    const bool aok = (rowBase + ar) < M;
    const float* Aptr = A + (size_t)(rowBase + ar) * K + ac4;
    const float* Bptr = B + (size_t)br * Nc + colBase + bc4;

    float4 acc[2][8];
#pragma unroll
    for (int mi = 0; mi < 2; mi++)
#pragma unroll
        for (int ni = 0; ni < 8; ni++) acc[mi][ni] = make_float4(0.f, 0.f, 0.f, 0.f);

#define SPLIT_STORE(arrH, arrL, BUF, D0, D1, V)                      \
    {                                                                \
        uint32_t h_ = f2tf(V);                                       \
        float lo_ = (V) - __uint_as_float(h_);                       \
        arrH[BUF][D0][D1] = h_;                                      \
        arrL[BUF][D0][D1] = f2tf(lo_);                               \
    }
#define LOAD_TILE(BUF, K0)                                                        \
    {                                                                             \
        float4 va = aok ? *(const float4*)(Aptr + (K0))                           \
                        : make_float4(0.f, 0.f, 0.f, 0.f);                        \
        float4 vb = *(const float4*)(Bptr + (size_t)(K0) * Nc);                   \
        SPLIT_STORE(Ah, Al, BUF, ac4 + 0, ar, va.x)                               \
        SPLIT_STORE(Ah, Al, BUF, ac4 + 1, ar, va.y)                               \
        SPLIT_STORE(Ah, Al, BUF, ac4 + 2, ar, va.z)                               \
        SPLIT_STORE(Ah, Al, BUF, ac4 + 3, ar, va.w)                               \
        SPLIT_STORE(Bh, Bl, BUF, br, bc4 + 0, vb.x)                               \
        SPLIT_STORE(Bh, Bl, BUF, br, bc4 + 1, vb.y)                               \
        SPLIT_STORE(Bh, Bl, BUF, br, bc4 + 2, vb.z)                               \
        SPLIT_STORE(Bh, Bl, BUF, br, bc4 + 3, vb.w)                               \
    }

#define COMPUTE_TILE(BUF)                                                          \
    {                                                                              \
        uint32_t ah[2][4], al[2][4];                                               \
        _Pragma("unroll")                                                          \
        for (int mi = 0; mi < 2; mi++) {                                           \
            int mrow = m0 + mi * 16;                                               \
            ah[mi][0] = Ah[BUF][t4][mrow + q];                                     \
            ah[mi][1] = Ah[BUF][t4][mrow + q + 8];                                 \
            ah[mi][2] = Ah[BUF][t4 + 4][mrow + q];                                 \
            ah[mi][3] = Ah[BUF][t4 + 4][mrow + q + 8];                             \
            al[mi][0] = Al[BUF][t4][mrow + q];                                     \
            al[mi][1] = Al[BUF][t4][mrow + q + 8];                                 \
            al[mi][2] = Al[BUF][t4 + 4][mrow + q];                                 \
            al[mi][3] = Al[BUF][t4 + 4][mrow + q + 8];                             \
        }                                                                          \
        _Pragma("unroll")                                                          \
        for (int ni = 0; ni < 8; ni++) {                                           \
            int ncol = n0 + ni * 8 + q;                                            \
            uint32_t bh0 = Bh[BUF][t4][ncol];                                      \
            uint32_t bh1 = Bh[BUF][t4 + 4][ncol];                                  \
            uint32_t bl0 = Bl[BUF][t4][ncol];                                      \
            uint32_t bl1 = Bl[BUF][t4 + 4][ncol];                                  \
            _Pragma("unroll")                                                      \
            for (int mi = 0; mi < 2; mi++) {                                       \
                mma_tf32(acc[mi][ni], ah[mi][0], ah[mi][1], ah[mi][2], ah[mi][3],  \
                         bh0, bh1);                                                \
                mma_tf32(acc[mi][ni], ah[mi][0], ah[mi][1], ah[mi][2], ah[mi][3],  \
                         bl0, bl1);                                                \
                mma_tf32(acc[mi][ni], al[mi][0], al[mi][1], al[mi][2], al[mi][3],  \
                         bh0, bh1);                                                \
            }                                                                      \
        }                                                                          \
    }

    LOAD_TILE(0, 0)
    __syncthreads();

    int buf = 0;
    for (int k0 = 8; k0 < K; k0 += 8) {
        COMPUTE_TILE(buf)
        LOAD_TILE(buf ^ 1, k0)
        __syncthreads();
        buf ^= 1;
    }
    COMPUTE_TILE(buf)

#pragma unroll
    for (int mi = 0; mi < 2; mi++) {
#pragma unroll
        for (int ni = 0; ni < 8; ni++) {
            int col = colBase + n0 + ni * 8 + 2 * t4;
            float bb0 = 0.f, bb1 = 0.f;
            if (epi) { bb0 = bias[col]; bb1 = bias[col + 1]; }
            int r0 = rowBase + m0 + mi * 16 + q;
            int r1 = r0 + 8;
            float4 v = acc[mi][ni];
            float o0 = v.x + bb0, o1 = v.y + bb1, o2 = v.z + bb0, o3 = v.w + bb1;
            if (epi) {
                o0 = fmaxf(o0, 0.f); o1 = fmaxf(o1, 0.f);
                o2 = fmaxf(o2, 0.f); o3 = fmaxf(o3, 0.f);
            }
            if (r0 < M) *(float2*)(Cm + (size_t)r0 * Nc + col) = make_float2(o0, o1);
            if (r1 < M) *(float2*)(Cm + (size_t)r1 * Nc + col) = make_float2(o2, o3);
        }
    }
}

// ---------------- softmax + argmax (first-max tie rule) ----------------------
__global__ void __launch_bounds__(256) k_softmax(const float* __restrict__ logits,
                                                 float* __restrict__ S) {
    int i = blockIdx.x;
    int t = threadIdx.x;
    int w = t >> 5, lane = t & 31;
    const float* row = logits + (size_t)i * CC;
    float v0 = row[t], v1 = row[t + 256];
    float bv = v0; int bi = t;
    if (v1 > bv) { bv = v1; bi = t + 256; }

#pragma unroll
    for (int off = 16; off > 0; off >>= 1) {
        float ov = __shfl_xor_sync(0xFFFFFFFF, bv, off);
        int   oi = __shfl_xor_sync(0xFFFFFFFF, bi, off);
        if (ov > bv || (ov == bv && oi < bi)) { bv = ov; bi = oi; }
    }
    __shared__ float swv[8];
    __shared__ int   swi[8];
    if (lane == 0) { swv[w] = bv; swi[w] = bi; }
    __syncthreads();
    float m = swv[0]; int am = swi[0];
#pragma unroll
    for (int k = 1; k < 8; k++) {
        float ov = swv[k]; int oi = swi[k];
        if (ov > m || (ov == m && oi < am)) { m = ov; am = oi; }
    }
    if (t == 0) g_cluster[i] = am;

    float e0 = expf(v0 - m), e1 = expf(v1 - m);
    float s = e0 + e1;
#pragma unroll
    for (int off = 16; off > 0; off >>= 1)
        s += __shfl_xor_sync(0xFFFFFFFF, s, off);
    __shared__ float sws[8];
    if (lane == 0) sws[w] = s;
    __syncthreads();
    float tot = sws[0] + sws[1] + sws[2] + sws[3] + sws[4] + sws[5] + sws[6] + sws[7];
    float invsum = 1.0f / tot;
    S[(size_t)i * CC + t]       = e0 * invsum;
    S[(size_t)i * CC + t + 256] = e1 * invsum;
}

// ---------------- score layer -------------------------------------------------
__global__ void k_hs(const float* __restrict__ x, const float* __restrict__ Ws) {
    int g = blockIdx.x * blockDim.x + threadIdx.x;
    int w = g >> 5, lane = g & 31;
    if (w >= NN) return;
    float4 xv = __ldg((const float4*)x + (size_t)w * 32 + lane);
    float4 wv = __ldg((const float4*)Ws + lane);
    float s = xv.x * wv.x + xv.y * wv.y + xv.z * wv.z + xv.w * wv.w;
#pragma unroll
    for (int off = 16; off > 0; off >>= 1) s += __shfl_down_sync(0xFFFFFFFF, s, off);
    if (lane == 0) g_hs[w] = s;
}

__global__ void k_intradeg(const int* __restrict__ ei) {
    int e = blockIdx.x * blockDim.x + threadIdx.x;
    if (e >= EE) return;
    int s = ei[e], d = ei[EE + e];
    int cs = g_cluster[s], cd = g_cluster[d];
    if (cs == cd) {
        atomicAdd(&g_sdeg[d], 1);
        atomicAdd(&g_icnt[cs], 1);
    }
}

__global__ void k_invs() {
    int i = blockIdx.x * blockDim.x + threadIdx.x;
    if (i < NN) g_invs[i] = rsqrtf((float)g_sdeg[i] + 1.0f);
}

__global__ void k_sagg(const int* __restrict__ ei) {
    int e = blockIdx.x * blockDim.x + threadIdx.x;
    if (e >= EE) return;
    int s = ei[e], d = ei[EE + e];
    if (g_cluster[s] == g_cluster[d])
        atomicAdd(&g_sagg[d], g_invs[s] * g_invs[d] * g_hs[s]);
}

__global__ void k_score(const float* __restrict__ bs) {
    int i = blockIdx.x * blockDim.x + threadIdx.x;
    if (i >= NN) return;
    float inv = g_invs[i];
    float v = g_sagg[i] + inv * inv * g_hs[i] + bs[0];
    float sc = tanhf(v);
    g_score[i] = sc;
    atomicMax(&g_segkey[g_cluster[i]], fkey(sc));
}

__global__ void k_segidx() {
    int i = blockIdx.x * blockDim.x + threadIdx.x;
    if (i >= NN) return;
    int c = g_cluster[i];
    float mx = fdec(g_segkey[c]);
    if (g_score[i] >= mx) atomicMin(&g_segidx[c], i);
}

// ---------------- pooling + adjacency ----------------------------------------
__global__ void __launch_bounds__(128) k_pool(const float* __restrict__ x,
                                              float* __restrict__ out) {
    int c = blockIdx.x;
    bool ne = g_icnt[c] > 0;
    float alpha = ne ? fdec(g_segkey[c]) : 0.f;
    int idx = min(g_segidx[c], NN - 1);
    out[(size_t)c * FF + threadIdx.x] = x[(size_t)idx * FF + threadIdx.x] * alpha;
}

__global__ void k_adj(const int* __restrict__ ei, float* __restrict__ out) {
    int e = blockIdx.x * blockDim.x + threadIdx.x;
    if (e >= EE) return;
    int cs = g_cluster[ei[e]], cd = g_cluster[ei[EE + e]];
    if (cs != cd && g_icnt[cs] > 0 && g_icnt[cd] > 0)
        out[OFF_ADJ + (size_t)cs * CC + cd] = 1.0f;
}

// ---------------- launch ------------------------------------------------------
extern "C" void kernel_launch(void* const* d_in, const int* in_sizes, int n_in,
                              void* d_out, int out_size) {
    const float* x   = (const float*)d_in[0];
    const int*   ei  = (const int*)d_in[1];
    const float* W1  = (const float*)d_in[3];
    const float* b1  = (const float*)d_in[4];
    const float* W2  = (const float*)d_in[5];
    const float* b2  = (const float*)d_in[6];
    const float* W3  = (const float*)d_in[7];
    const float* b3  = (const float*)d_in[8];
    const float* Ws  = (const float*)d_in[9];
    const float* bs  = (const float*)d_in[10];
    float* out = (float*)d_out;

    const int EB = (EE + 255) / 256;
    const int NB = (NN + 255) / 256;
    const int GX = (NN + 3) / 4;

    k_init<<<512, 256>>>(out);
    k_deg<<<EB, 256>>>(ei);
    k_scanall<<<1, 1024>>>();
    k_fill<<<EB, 256>>>(ei);

    // layer 1: z = Ahat x (tiled); h1 = relu(z @ W1 + b1)
    k_aggt<128><<<dim3(GX, 128 / 64), 256>>>(x, g_z);
    {
        dim3 g(HH / 128, (NN + 127) / 128);
        k_tcgemm<<<g, 256>>>(g_z, W1, b1, g_t, NN, FF, HH, 1);
    }
    // layer 2
    k_aggt<256><<<dim3(GX, 256 / 64), 256>>>(g_t, g_z);
    {
        dim3 g(HH / 128, (NN + 127) / 128);
        k_tcgemm<<<g, 256>>>(g_z, W2, b2, g_t, NN, HH, HH, 1);
    }
    // layer 3
    k_aggt<256><<<dim3(GX, 256 / 64), 256>>>(g_t, g_z);
    {
        dim3 g(CC / 128, (NN + 127) / 128);
        k_tcgemm<<<g, 256>>>(g_z, W3, b3, g_l, NN, HH, CC, 1);
    }

    k_softmax<<<NN, 256>>>(g_l, out + OFF_S);

    k_hs<<<(NN * 32 + 255) / 256, 256>>>(x, Ws);
    k_intradeg<<<EB, 256>>>(ei);
    k_invs<<<NB, 256>>>();
    k_sagg<<<EB, 256>>>(ei);
    k_score<<<NB, 256>>>(bs);
    k_segidx<<<NB, 256>>>();
    k_pool<<<CC, 128>>>(x, out);
    k_adj<<<EB, 256>>>(ei, out);

    (void)in_sizes; (void)n_in; (void)out_size;
}